// round 5
// baseline (speedup 1.0000x reference)
#include <cuda_runtime.h>
#include <math.h>

#define BNN   81920
#define NEDGE 327680
#define NT    16

typedef unsigned long long u64;

// ------------------------------ scratch (static device memory; no allocs) ---
__device__ __align__(256) float g_deg[BNN];
__device__ __align__(256) float g_dinv[BNN];
__device__ __align__(256) int   g_rowptr[BNN + 1];
__device__ __align__(256) int   g_fill[BNN];
__device__ __align__(256) int   g_csr_src[NEDGE];
__device__ __align__(256) float g_csr_w[NEDGE];
__device__ __align__(256) float g_P1[BNN * 64];
__device__ __align__(256) float g_P2[BNN * 64];
__device__ __align__(256) float g_Gx[BNN * 192];
__device__ __align__(256) float g_Gh[BNN * 128];
__device__ __align__(256) float g_Ghh[BNN * 64];
__device__ __align__(256) float g_Hst[BNN * 64];
__device__ __align__(256) float g_Zst[BNN * 64];
__device__ __align__(256) float g_HRst[BNN * 64];
__device__ __align__(256) float g_Wx[192 * 192];
__device__ __align__(256) float g_Whp[192 * 128];
__device__ __align__(256) float g_Whhp[192 * 64];
__device__ __align__(256) float g_bxp[192];
__device__ __align__(256) float g_bhp[128];
__device__ __align__(256) float g_bhhp[64];
__device__ __align__(256) float g_M1[4096 * 640];
__device__ __align__(256) float g_M2[4096 * 320];

// ------------------------------ f32x2 helpers (FFMA2 path) ------------------
__device__ __forceinline__ u64 ffma2(u64 a, u64 b, u64 c) {
    u64 d;
    asm("fma.rn.f32x2 %0, %1, %2, %3;" : "=l"(d) : "l"(a), "l"(b), "l"(c));
    return d;
}
__device__ __forceinline__ u64 pack2(float lo, float hi) {
    u64 d;
    asm("mov.b64 %0, {%1, %2};" : "=l"(d) : "f"(lo), "f"(hi));
    return d;
}
__device__ __forceinline__ void unpack2(u64 v, float& lo, float& hi) {
    asm("mov.b64 {%0, %1}, %2;" : "=f"(lo), "=f"(hi) : "l"(v));
}

// ------------------------------ graph preprocessing -------------------------
__global__ void k_deg(const int* __restrict__ src, const float* __restrict__ w) {
    int e = blockIdx.x * 256 + threadIdx.x;
    atomicAdd(&g_deg[src[e]], w[e]);
}

__global__ void k_dinv() {
    int n = blockIdx.x * 256 + threadIdx.x;
    float d = g_deg[n];
    g_dinv[n] = (d > 0.f) ? rsqrtf(d) : 0.f;
}

__global__ void k_count(const int* __restrict__ dst) {
    int e = blockIdx.x * 256 + threadIdx.x;
    atomicAdd(&g_fill[dst[e]], 1);
}

__global__ void k_scan() {  // 1 block, 1024 threads: exclusive scan of g_fill -> g_rowptr
    const int tid = threadIdx.x;
    const int lane = tid & 31;
    const int wp = tid >> 5;
    __shared__ int wsum[32];
    __shared__ int carry;
    if (tid == 0) carry = 0;
    __syncthreads();
    for (int c = 0; c < BNN; c += 1024) {
        int v = g_fill[c + tid];
        int x = v;
#pragma unroll
        for (int off = 1; off < 32; off <<= 1) {
            int nbr = __shfl_up_sync(0xffffffffu, x, off);
            if (lane >= off) x += nbr;
        }
        if (lane == 31) wsum[wp] = x;
        __syncthreads();
        if (wp == 0) {
            int y = wsum[lane];
#pragma unroll
            for (int off = 1; off < 32; off <<= 1) {
                int nbr = __shfl_up_sync(0xffffffffu, y, off);
                if (lane >= off) y += nbr;
            }
            wsum[lane] = y;
        }
        __syncthreads();
        int base = carry + ((wp > 0) ? wsum[wp - 1] : 0);
        g_rowptr[c + tid] = base + x - v;
        __syncthreads();
        if (tid == 1023) carry += wsum[31];
        __syncthreads();
    }
    if (tid == 0) g_rowptr[BNN] = carry;
}

__global__ void k_copyfill() {
    int n = blockIdx.x * 256 + threadIdx.x;
    g_fill[n] = g_rowptr[n];
}

__global__ void k_fillcsr(const int* __restrict__ src, const int* __restrict__ dst,
                          const float* __restrict__ w) {
    int e = blockIdx.x * 256 + threadIdx.x;
    int s = src[e], d = dst[e];
    float wn = -g_dinv[s] * w[e] * g_dinv[d];
    int pos = atomicAdd(&g_fill[d], 1);
    g_csr_src[pos] = s;
    g_csr_w[pos] = wn;
}

// ------------------------------ weight packing ------------------------------
__global__ void k_pack(const float* __restrict__ Wxz, const float* __restrict__ Wxr,
                       const float* __restrict__ Wxh, const float* __restrict__ Whz,
                       const float* __restrict__ Whr, const float* __restrict__ Whh,
                       const float* __restrict__ bxz, const float* __restrict__ bxr,
                       const float* __restrict__ bxh, const float* __restrict__ bhz,
                       const float* __restrict__ bhr, const float* __restrict__ bhh) {
    int i = blockIdx.x * 256 + threadIdx.x;
    if (i < 36864) {                       // Wx [192,192], cols = [z|r|h]
        int row = i / 192, col = i % 192;
        int k = row >> 6, ii = row & 63, g = col >> 6, j = col & 63;
        const float* Wg = (g == 0) ? Wxz : ((g == 1) ? Wxr : Wxh);
        g_Wx[i] = Wg[k * 4096 + ii * 64 + j];
    } else if (i < 61440) {                // Wh [192,128], cols = [z|r]
        int t = i - 36864;
        int row = t / 128, col = t % 128;
        int k = row >> 6, ii = row & 63, g = col >> 6, j = col & 63;
        const float* Wg = g ? Whr : Whz;
        g_Whp[t] = Wg[k * 4096 + ii * 64 + j];
    } else if (i < 73728) {                // Whh [192,64]
        int t = i - 61440;
        int row = t >> 6, col = t & 63;
        int k = row >> 6, ii = row & 63;
        g_Whhp[t] = Whh[k * 4096 + ii * 64 + col];
    } else if (i < 73920) {
        int col = i - 73728;
        int g = col >> 6, j = col & 63;
        g_bxp[col] = (g == 0) ? bxz[j] : ((g == 1) ? bxr[j] : bxh[j]);
    } else if (i < 74048) {
        int col = i - 73920;
        g_bhp[col] = (col < 64) ? bhz[col] : bhr[col - 64];
    } else if (i < 74112) {
        g_bhhp[i - 74048] = bhh[i - 74048];
    }
}

// ------------------------------ sparse propagation --------------------------
// out[n] = alpha * sum_{e into n} w[e]*X[src[e]]   (+ beta*base[n] if beta!=0)
__global__ void k_prop(const float4* __restrict__ X, float4* __restrict__ out,
                       float alpha, const float4* __restrict__ base, float beta) {
    int t = blockIdx.x * 128 + threadIdx.x;
    int node = t >> 4;
    int l = t & 15;
    int s = g_rowptr[node], e = g_rowptr[node + 1];
    float ax = 0.f, ay = 0.f, az = 0.f, aw = 0.f;
    for (int i = s; i < e; i++) {
        int src = g_csr_src[i];
        float w = g_csr_w[i];
        float4 v = X[src * 16 + l];
        ax += w * v.x; ay += w * v.y; az += w * v.z; aw += w * v.w;
    }
    float4 r;
    r.x = alpha * ax; r.y = alpha * ay; r.z = alpha * az; r.w = alpha * aw;
    if (beta != 0.f) {
        float4 b = base[node * 16 + l];
        r.x += beta * b.x; r.y += beta * b.y; r.z += beta * b.z; r.w += beta * b.w;
    }
    out[node * 16 + l] = r;
}

// ------------------------------ tiled SGEMM (f32x2) -------------------------
// THREE: A = [A0|A1|A2] concatenated along K (each [M,64], lda=64), Ktot=192.
// else : A = A0 with lda = K. C[M,N] = act(A@W + bias). BM=128, BN=64, BK=32.
template <bool THREE, bool RELU>
__global__ __launch_bounds__(256) void k_gemm(
    const float* __restrict__ A0, const float* __restrict__ A1,
    const float* __restrict__ A2, int K, const float* __restrict__ W,
    const float* __restrict__ bias, float* __restrict__ C, int N) {
    __shared__ float As[32][132];
    __shared__ float Ws[32][64];
    const int tid = threadIdx.x;
    const int tx = tid & 15;
    const int ty = tid >> 4;
    const int m0 = blockIdx.y * 128;
    const int n0 = blockIdx.x * 64;

    u64 acc[4][4];
#pragma unroll
    for (int i = 0; i < 4; i++)
#pragma unroll
        for (int j = 0; j < 4; j++) acc[i][j] = 0ull;

    const int mload = tid >> 3;
    const int kq = (tid & 7) << 2;
    const int wk = tid >> 4;
    const int wn = (tid & 15) << 2;

    const int nk = THREE ? 6 : (K >> 5);
    for (int kt = 0; kt < nk; kt++) {
        const int k0 = kt << 5;
        const float* Ap;
        int lda, kloc;
        if (THREE) {
            const int bsel = k0 >> 6;
            Ap = (bsel == 0) ? A0 : ((bsel == 1) ? A1 : A2);
            kloc = k0 & 63;
            lda = 64;
        } else {
            Ap = A0; kloc = k0; lda = K;
        }
#pragma unroll
        for (int r = 0; r < 4; r++) {
            float4 v = *reinterpret_cast<const float4*>(
                Ap + (size_t)(m0 + mload + r * 32) * lda + kloc + kq);
            As[kq + 0][mload + r * 32] = v.x;
            As[kq + 1][mload + r * 32] = v.y;
            As[kq + 2][mload + r * 32] = v.z;
            As[kq + 3][mload + r * 32] = v.w;
        }
#pragma unroll
        for (int r = 0; r < 2; r++) {
            float4 v = *reinterpret_cast<const float4*>(
                W + (size_t)(k0 + wk + r * 16) * N + n0 + wn);
            *reinterpret_cast<float4*>(&Ws[wk + r * 16][wn]) = v;
        }
        __syncthreads();
#pragma unroll
        for (int k = 0; k < 32; k++) {
            float4 a0v = *reinterpret_cast<const float4*>(&As[k][ty * 8]);
            float4 a1v = *reinterpret_cast<const float4*>(&As[k][ty * 8 + 4]);
            float4 bv = *reinterpret_cast<const float4*>(&Ws[k][tx * 4]);
            u64 ap[4] = {pack2(a0v.x, a0v.y), pack2(a0v.z, a0v.w),
                         pack2(a1v.x, a1v.y), pack2(a1v.z, a1v.w)};
            u64 bb[4] = {pack2(bv.x, bv.x), pack2(bv.y, bv.y),
                         pack2(bv.z, bv.z), pack2(bv.w, bv.w)};
#pragma unroll
            for (int i = 0; i < 4; i++)
#pragma unroll
                for (int j = 0; j < 4; j++)
                    acc[i][j] = ffma2(ap[i], bb[j], acc[i][j]);
        }
        __syncthreads();
    }

    const int col = n0 + tx * 4;
    float b0 = bias[col], b1 = bias[col + 1], b2 = bias[col + 2], b3 = bias[col + 3];
#pragma unroll
    for (int i = 0; i < 4; i++) {
        float lo0, hi0, lo1, hi1, lo2, hi2, lo3, hi3;
        unpack2(acc[i][0], lo0, hi0);
        unpack2(acc[i][1], lo1, hi1);
        unpack2(acc[i][2], lo2, hi2);
        unpack2(acc[i][3], lo3, hi3);
        const int row = m0 + ty * 8 + i * 2;
        float4 r0 = make_float4(lo0 + b0, lo1 + b1, lo2 + b2, lo3 + b3);
        float4 r1 = make_float4(hi0 + b0, hi1 + b1, hi2 + b2, hi3 + b3);
        if (RELU) {
            r0.x = fmaxf(r0.x, 0.f); r0.y = fmaxf(r0.y, 0.f);
            r0.z = fmaxf(r0.z, 0.f); r0.w = fmaxf(r0.w, 0.f);
            r1.x = fmaxf(r1.x, 0.f); r1.y = fmaxf(r1.y, 0.f);
            r1.z = fmaxf(r1.z, 0.f); r1.w = fmaxf(r1.w, 0.f);
        }
        *reinterpret_cast<float4*>(C + (size_t)row * N + col) = r0;
        *reinterpret_cast<float4*>(C + (size_t)(row + 1) * N + col) = r1;
    }
}

// ------------------------------ GRU gate fusion -----------------------------
__device__ __forceinline__ float sigf(float x) { return 1.f / (1.f + expf(-x)); }

__global__ void k_gateZR() {  // Z = sig(Gx_z+Gh_z); R = sig(Gx_r+Gh_r); HR = H*R
    int i = blockIdx.x * 256 + threadIdx.x;  // over BNN*16 float4s
    int n = i >> 4, l = i & 15;
    const float4* Gx = reinterpret_cast<const float4*>(g_Gx);
    const float4* Gh = reinterpret_cast<const float4*>(g_Gh);
    const float4* H = reinterpret_cast<const float4*>(g_Hst);
    float4* Z = reinterpret_cast<float4*>(g_Zst);
    float4* HR = reinterpret_cast<float4*>(g_HRst);
    float4 gz = Gx[(size_t)n * 48 + l];
    float4 gr = Gx[(size_t)n * 48 + 16 + l];
    float4 hz = Gh[(size_t)n * 32 + l];
    float4 hr = Gh[(size_t)n * 32 + 16 + l];
    float4 h = H[(size_t)n * 16 + l];
    float4 z, r, o;
    z.x = sigf(gz.x + hz.x); z.y = sigf(gz.y + hz.y);
    z.z = sigf(gz.z + hz.z); z.w = sigf(gz.w + hz.w);
    r.x = sigf(gr.x + hr.x); r.y = sigf(gr.y + hr.y);
    r.z = sigf(gr.z + hr.z); r.w = sigf(gr.w + hr.w);
    o.x = h.x * r.x; o.y = h.y * r.y; o.z = h.z * r.z; o.w = h.w * r.w;
    Z[(size_t)n * 16 + l] = z;
    HR[(size_t)n * 16 + l] = o;
}

__global__ void k_gateH() {  // Ht = tanh(Gx_h+Ghh); H = relu(Z*H + (1-Z)*Ht)
    int i = blockIdx.x * 256 + threadIdx.x;
    int n = i >> 4, l = i & 15;
    const float4* Gx = reinterpret_cast<const float4*>(g_Gx);
    const float4* Gg = reinterpret_cast<const float4*>(g_Ghh);
    const float4* Z = reinterpret_cast<const float4*>(g_Zst);
    float4* H = reinterpret_cast<float4*>(g_Hst);
    float4 gh = Gx[(size_t)n * 48 + 32 + l];
    float4 gg = Gg[(size_t)n * 16 + l];
    float4 z = Z[(size_t)n * 16 + l];
    float4 h = H[(size_t)n * 16 + l];
    float4 o;
    float t;
    t = tanhf(gh.x + gg.x); o.x = fmaxf(z.x * h.x + (1.f - z.x) * t, 0.f);
    t = tanhf(gh.y + gg.y); o.y = fmaxf(z.y * h.y + (1.f - z.y) * t, 0.f);
    t = tanhf(gh.z + gg.z); o.z = fmaxf(z.z * h.z + (1.f - z.z) * t, 0.f);
    t = tanhf(gh.w + gg.w); o.w = fmaxf(z.w * h.w + (1.f - z.w) * t, 0.f);
    H[(size_t)n * 16 + l] = o;
}

// ------------------------------ final layer + softmax -----------------------
__global__ void k_out(const float* __restrict__ A, const float* __restrict__ W3,
                      const float* __restrict__ b3, float* __restrict__ out) {
    int warp = threadIdx.x >> 5, lane = threadIdx.x & 31;
    int row = blockIdx.x * 8 + warp;
    float s0 = 0.f, s1 = 0.f;
    for (int k = lane; k < 320; k += 32) {
        float a = A[row * 320 + k];
        s0 += a * W3[k * 2];
        s1 += a * W3[k * 2 + 1];
    }
#pragma unroll
    for (int off = 16; off; off >>= 1) {
        s0 += __shfl_xor_sync(0xffffffffu, s0, off);
        s1 += __shfl_xor_sync(0xffffffffu, s1, off);
    }
    if (lane == 0) {
        float l0 = s0 + b3[0], l1 = s1 + b3[1];
        float m = fmaxf(l0, l1);
        float e0 = expf(l0 - m), e1 = expf(l1 - m);
        float inv = 1.f / (e0 + e1);
        out[row * 2] = e0 * inv;
        out[row * 2 + 1] = e1 * inv;
    }
}

// ------------------------------ launch --------------------------------------
extern "C" void kernel_launch(void* const* d_in, const int* in_sizes, int n_in,
                              void* d_out, int out_size) {
    const float* x = (const float*)d_in[0];
    const int* ei = (const int*)d_in[1];
    const float* ew = (const float*)d_in[2];
    const float* Wxz = (const float*)d_in[3];  const float* bxz = (const float*)d_in[4];
    const float* Whz = (const float*)d_in[5];  const float* bhz = (const float*)d_in[6];
    const float* Wxr = (const float*)d_in[7];  const float* bxr = (const float*)d_in[8];
    const float* Whr = (const float*)d_in[9];  const float* bhr = (const float*)d_in[10];
    const float* Wxh = (const float*)d_in[11]; const float* bxh = (const float*)d_in[12];
    const float* Whh = (const float*)d_in[13]; const float* bhh = (const float*)d_in[14];
    const float* W1 = (const float*)d_in[15];  const float* b1 = (const float*)d_in[16];
    const float* W2 = (const float*)d_in[17];  const float* b2 = (const float*)d_in[18];
    const float* W3 = (const float*)d_in[19];  const float* b3 = (const float*)d_in[20];
    float* out = (float*)d_out;
    const int* src = ei;
    const int* dst = ei + NEDGE;

    float *pDeg, *pP1, *pP2, *pGx, *pGh, *pGhh, *pH, *pM1, *pM2;
    float *pWx, *pWh, *pWhh, *pbx, *pbh, *pbhh, *pHR;
    int* pFill;
    cudaGetSymbolAddress((void**)&pDeg, g_deg);
    cudaGetSymbolAddress((void**)&pFill, g_fill);
    cudaGetSymbolAddress((void**)&pP1, g_P1);
    cudaGetSymbolAddress((void**)&pP2, g_P2);
    cudaGetSymbolAddress((void**)&pGx, g_Gx);
    cudaGetSymbolAddress((void**)&pGh, g_Gh);
    cudaGetSymbolAddress((void**)&pGhh, g_Ghh);
    cudaGetSymbolAddress((void**)&pH, g_Hst);
    cudaGetSymbolAddress((void**)&pHR, g_HRst);
    cudaGetSymbolAddress((void**)&pWx, g_Wx);
    cudaGetSymbolAddress((void**)&pWh, g_Whp);
    cudaGetSymbolAddress((void**)&pWhh, g_Whhp);
    cudaGetSymbolAddress((void**)&pbx, g_bxp);
    cudaGetSymbolAddress((void**)&pbh, g_bhp);
    cudaGetSymbolAddress((void**)&pbhh, g_bhhp);
    cudaGetSymbolAddress((void**)&pM1, g_M1);
    cudaGetSymbolAddress((void**)&pM2, g_M2);

    // ---- preprocessing (per launch; deterministic) ----
    cudaMemsetAsync(pDeg, 0, BNN * sizeof(float));
    cudaMemsetAsync(pFill, 0, BNN * sizeof(int));
    cudaMemsetAsync(pH, 0, (size_t)BNN * 64 * sizeof(float));
    k_deg<<<NEDGE / 256, 256>>>(src, ew);
    k_dinv<<<BNN / 256, 256>>>();
    k_count<<<NEDGE / 256, 256>>>(dst);
    k_scan<<<1, 1024>>>();
    k_copyfill<<<BNN / 256, 256>>>();
    k_fillcsr<<<NEDGE / 256, 256>>>(src, dst, ew);
    k_pack<<<(74112 + 255) / 256, 256>>>(Wxz, Wxr, Wxh, Whz, Whr, Whh,
                                         bxz, bxr, bxh, bhz, bhr, bhh);

    const int propGrid = BNN * 16 / 128;  // 10240
    const int ewGrid = BNN * 16 / 256;    // 5120

    // ---- GConvGRU over T timesteps ----
    for (int t = 0; t < NT; t++) {
        const float* Xt = x + (size_t)t * BNN * 64;
        // X-side Chebyshev basis + fused gate GEMM ([X|LX|2L^2X-X] @ Wx)
        k_prop<<<propGrid, 128>>>((const float4*)Xt, (float4*)pP1, 1.f, nullptr, 0.f);
        k_prop<<<propGrid, 128>>>((const float4*)pP1, (float4*)pP2, 2.f,
                                  (const float4*)Xt, -1.f);
        k_gemm<true, false><<<dim3(3, 640), 256>>>(Xt, pP1, pP2, 192, pWx, pbx, pGx, 192);
        // H-side basis + (z,r) GEMM
        k_prop<<<propGrid, 128>>>((const float4*)pH, (float4*)pP1, 1.f, nullptr, 0.f);
        k_prop<<<propGrid, 128>>>((const float4*)pP1, (float4*)pP2, 2.f,
                                  (const float4*)pH, -1.f);
        k_gemm<true, false><<<dim3(2, 640), 256>>>(pH, pP1, pP2, 192, pWh, pbh, pGh, 128);
        // gates Z, R and HR = H*R
        k_gateZR<<<ewGrid, 256>>>();
        // HR-side basis + hh GEMM
        k_prop<<<propGrid, 128>>>((const float4*)pHR, (float4*)pP1, 1.f, nullptr, 0.f);
        k_prop<<<propGrid, 128>>>((const float4*)pP1, (float4*)pP2, 2.f,
                                  (const float4*)pHR, -1.f);
        k_gemm<true, false><<<dim3(1, 640), 256>>>(pHR, pP1, pP2, 192, pWhh, pbhh, pGhh, 64);
        // H update
        k_gateH<<<ewGrid, 256>>>();
    }

    // ---- MLP head: H reshaped to [4096, 1280] ----
    k_gemm<false, true><<<dim3(10, 32), 256>>>(pH, nullptr, nullptr, 1280, W1, b1, pM1, 640);
    k_gemm<false, true><<<dim3(5, 32), 256>>>(pM1, nullptr, nullptr, 640, W2, b2, pM2, 320);
    k_out<<<512, 256>>>(pM2, W3, b3, out);
}

// round 8
// speedup vs baseline: 1.4884x; 1.4884x over previous
#include <cuda_runtime.h>
#include <math.h>
#include <stdint.h>

#define BNN   81920
#define NEDGE 327680
#define NT    16

// ---------------- static device scratch ----------------
__device__ __align__(256) float g_deg[BNN];
__device__ __align__(256) float g_dinv[BNN];
__device__ __align__(256) int   g_rowptr[BNN + 1];
__device__ __align__(256) int   g_fill[BNN];
__device__ __align__(256) int   g_bsum[80];
__device__ __align__(256) int   g_boff[80];
__device__ __align__(256) int   g_csr_src[NEDGE];
__device__ __align__(256) float g_csr_w[NEDGE];
__device__ __align__(256) float g_P1[BNN * 64];
__device__ __align__(256) float g_P2[BNN * 64];
__device__ __align__(256) float g_P3[BNN * 64];
__device__ __align__(256) float g_P4[BNN * 64];
__device__ __align__(256) float g_Z[BNN * 64];
__device__ __align__(256) float g_HR[BNN * 64];
__device__ __align__(256) float g_Gxh[BNN * 64];
__device__ __align__(256) float g_Hst[BNN * 64];
__device__ __align__(256) float g_WB1[192 * 384];   // [N][K] gates z|r|h
__device__ __align__(256) float g_WB2[64 * 192];    // [N][K] hh
__device__ __align__(256) float g_WB3[640 * 1280];  // W1^T
__device__ __align__(256) float g_WB4[320 * 640];   // W2^T
__device__ __align__(256) float g_bc1[192];
__device__ __align__(256) float g_M1[4096 * 640];
__device__ __align__(256) float g_M2[4096 * 320];

// ---------------- helpers ----------------
__device__ __forceinline__ uint32_t f2tf(float f) {
    uint32_t r;
    asm("cvt.rna.tf32.f32 %0, %1;" : "=r"(r) : "f"(f));
    return r;
}
__device__ __forceinline__ void mma8(float* d, const uint32_t* a, const uint32_t* b) {
    asm volatile(
        "mma.sync.aligned.m16n8k8.row.col.f32.tf32.tf32.f32 "
        "{%0,%1,%2,%3}, {%4,%5,%6,%7}, {%8,%9}, {%0,%1,%2,%3};"
        : "+f"(d[0]), "+f"(d[1]), "+f"(d[2]), "+f"(d[3])
        : "r"(a[0]), "r"(a[1]), "r"(a[2]), "r"(a[3]), "r"(b[0]), "r"(b[1]));
}
__device__ __forceinline__ float sigf(float x) { return 1.f / (1.f + expf(-x)); }

// ---------------- graph preprocessing ----------------
__global__ void k_degcnt(const int* __restrict__ src, const int* __restrict__ dst,
                         const float* __restrict__ w) {
    int e = blockIdx.x * 256 + threadIdx.x;
    atomicAdd(&g_deg[src[e]], w[e]);
    atomicAdd(&g_fill[dst[e]], 1);
}
__global__ void k_dinv() {
    int n = blockIdx.x * 256 + threadIdx.x;
    float d = g_deg[n];
    g_dinv[n] = (d > 0.f) ? rsqrtf(d) : 0.f;
}
__global__ void k_scanA() {  // 80 x 1024
    int tid = threadIdx.x, lane = tid & 31, wp = tid >> 5, b = blockIdx.x;
    __shared__ int wsum[32];
    int v = g_fill[b * 1024 + tid], x = v;
#pragma unroll
    for (int o = 1; o < 32; o <<= 1) {
        int n = __shfl_up_sync(0xffffffffu, x, o);
        if (lane >= o) x += n;
    }
    if (lane == 31) wsum[wp] = x;
    __syncthreads();
    if (wp == 0) {
        int y = wsum[lane];
#pragma unroll
        for (int o = 1; o < 32; o <<= 1) {
            int n = __shfl_up_sync(0xffffffffu, y, o);
            if (lane >= o) y += n;
        }
        wsum[lane] = y;
    }
    __syncthreads();
    int base = (wp > 0) ? wsum[wp - 1] : 0;
    g_rowptr[b * 1024 + tid] = base + x - v;
    if (tid == 1023) g_bsum[b] = base + x;
}
__global__ void k_scanB() {  // 1 x 32
    int lane = threadIdx.x;
    int carry = 0;
    for (int base = 0; base < 80; base += 32) {
        int v = (base + lane < 80) ? g_bsum[base + lane] : 0, x = v;
#pragma unroll
        for (int o = 1; o < 32; o <<= 1) {
            int n = __shfl_up_sync(0xffffffffu, x, o);
            if (lane >= o) x += n;
        }
        if (base + lane < 80) g_boff[base + lane] = carry + x - v;
        carry += __shfl_sync(0xffffffffu, x, 31);
    }
    if (lane == 0) g_rowptr[BNN] = carry;
}
__global__ void k_scanC() {  // 80 x 1024
    int i = blockIdx.x * 1024 + threadIdx.x;
    int r = g_rowptr[i] + g_boff[blockIdx.x];
    g_rowptr[i] = r;
    g_fill[i] = r;
}
__global__ void k_fillcsr(const int* __restrict__ src, const int* __restrict__ dst,
                          const float* __restrict__ w) {
    int e = blockIdx.x * 256 + threadIdx.x;
    int s = src[e], d = dst[e];
    float wn = -g_dinv[s] * w[e] * g_dinv[d];
    int pos = atomicAdd(&g_fill[d], 1);
    g_csr_src[pos] = s;
    g_csr_w[pos] = wn;
}

// ---------------- weight packing (B stored [N][K] row-major) ----------------
__global__ void k_packW(const float* __restrict__ Wxz, const float* __restrict__ Wxr,
                        const float* __restrict__ Wxh, const float* __restrict__ Whz,
                        const float* __restrict__ Whr, const float* __restrict__ Whh,
                        const float* __restrict__ bxz, const float* __restrict__ bxr,
                        const float* __restrict__ bxh, const float* __restrict__ bhz,
                        const float* __restrict__ bhr,
                        const float* __restrict__ W1, const float* __restrict__ W2) {
    int idx = blockIdx.x * 256 + threadIdx.x;
    if (idx < 73728) {  // WB1 [192][384]
        int n = idx / 384, k = idx % 384;
        float v;
        if (k < 192) {
            int kb = k >> 6, j = k & 63;
            const float* W = (n < 64) ? Wxz : ((n < 128) ? Wxr : Wxh);
            v = W[kb * 4096 + j * 64 + (n & 63)];
        } else {
            int k2 = k - 192, kb = k2 >> 6, j = k2 & 63;
            if (n < 64) v = Whz[kb * 4096 + j * 64 + n];
            else if (n < 128) v = Whr[kb * 4096 + j * 64 + (n - 64)];
            else v = 0.f;
        }
        g_WB1[idx] = v;
    } else if (idx < 86016) {  // WB2 [64][192]
        int t = idx - 73728;
        int n = t / 192, k = t % 192, kb = k >> 6, j = k & 63;
        g_WB2[t] = Whh[kb * 4096 + j * 64 + n];
    } else if (idx < 905216) {  // WB3 [640][1280] = W1^T
        int t = idx - 86016;
        int n = t / 1280, k = t % 1280;
        g_WB3[t] = W1[k * 640 + n];
    } else if (idx < 1110016) {  // WB4 [320][640] = W2^T
        int t = idx - 905216;
        int n = t / 640, k = t % 640;
        g_WB4[t] = W2[k * 320 + n];
    } else if (idx < 1110208) {
        int c = idx - 1110016;
        float v;
        if (c < 64) v = bxz[c] + bhz[c];
        else if (c < 128) v = bxr[c - 64] + bhr[c - 64];
        else v = bxh[c - 128];
        g_bc1[c] = v;
    }
}

// ---------------- sparse propagation ----------------
__global__ void k_prop(const float4* __restrict__ X, float4* __restrict__ out,
                       float alpha, const float4* __restrict__ base, float beta) {
    int t = blockIdx.x * 128 + threadIdx.x;
    int node = t >> 4, l = t & 15;
    int s = g_rowptr[node], e = g_rowptr[node + 1];
    float ax = 0.f, ay = 0.f, az = 0.f, aw = 0.f;
    for (int i = s; i < e; i++) {
        int sc = g_csr_src[i];
        float w = g_csr_w[i];
        float4 v = X[sc * 16 + l];
        ax += w * v.x; ay += w * v.y; az += w * v.z; aw += w * v.w;
    }
    float4 r;
    r.x = alpha * ax; r.y = alpha * ay; r.z = alpha * az; r.w = alpha * aw;
    if (beta != 0.f) {
        float4 b = base[node * 16 + l];
        r.x += beta * b.x; r.y += beta * b.y; r.z += beta * b.z; r.w += beta * b.w;
    }
    out[node * 16 + l] = r;
}

// ---------------- tf32 mma.sync GEMM: block 128x64, 8 warps ----------------
// C[M,N] = A[M,K] @ W^T, W stored [N][K]. EPI 0: gate epilogue (N=192,
// section = blockIdx.x). EPI 1: GRU update -> H. EPI 2: relu(v+bias) -> C.
struct Args {
    const float* a0; const float* a1; const float* a2;
    const float* a3; const float* a4; const float* a5;
    int astride; int nk; int ktot;
    const float* B; const float* bias;
    float* C; int ldc;
};

template <int EPI, bool MULTI>
__global__ __launch_bounds__(256) void k_mma(Args a) {
    __shared__ uint32_t As[128][33];
    __shared__ uint32_t Bs[64][33];
    const int tid = threadIdx.x, wid = tid >> 5, lane = tid & 31;
    const int wm = (wid & 3) * 32, wn = (wid >> 2) * 32;
    const int m0 = blockIdx.y * 128, n0 = blockIdx.x * 64;

    float acc[2][4][4];
#pragma unroll
    for (int i = 0; i < 2; i++)
#pragma unroll
        for (int j = 0; j < 4; j++)
#pragma unroll
            for (int q = 0; q < 4; q++) acc[i][j][q] = 0.f;

    const int arow = tid >> 1, acb = (tid & 1) * 16;
    const int brow = tid >> 2, bcb = (tid & 3) * 8;

    for (int c = 0; c < a.nk; c++) {
        const float* Ap;
        int koff, rs;
        if (MULTI) {
            int sel = c >> 1;
            Ap = (sel == 0) ? a.a0 : (sel == 1) ? a.a1 : (sel == 2) ? a.a2
                 : (sel == 3) ? a.a3 : (sel == 4) ? a.a4 : a.a5;
            koff = (c & 1) * 32;
            rs = 64;
        } else {
            Ap = a.a0; koff = c * 32; rs = a.astride;
        }
        __syncthreads();
        {
            const float* rp = Ap + (size_t)(m0 + arow) * rs + koff + acb;
#pragma unroll
            for (int j = 0; j < 4; j++) {
                float4 v = *(const float4*)(rp + j * 4);
                As[arow][acb + j * 4 + 0] = f2tf(v.x);
                As[arow][acb + j * 4 + 1] = f2tf(v.y);
                As[arow][acb + j * 4 + 2] = f2tf(v.z);
                As[arow][acb + j * 4 + 3] = f2tf(v.w);
            }
        }
        {
            const float* rp = a.B + (size_t)(n0 + brow) * a.ktot + c * 32 + bcb;
#pragma unroll
            for (int j = 0; j < 2; j++) {
                float4 v = *(const float4*)(rp + j * 4);
                Bs[brow][bcb + j * 4 + 0] = f2tf(v.x);
                Bs[brow][bcb + j * 4 + 1] = f2tf(v.y);
                Bs[brow][bcb + j * 4 + 2] = f2tf(v.z);
                Bs[brow][bcb + j * 4 + 3] = f2tf(v.w);
            }
        }
        __syncthreads();
#pragma unroll
        for (int ks = 0; ks < 4; ks++) {
            const int kb = ks * 8;
            uint32_t af[2][4], bf[4][2];
#pragma unroll
            for (int mt = 0; mt < 2; mt++) {
                int r = wm + mt * 16 + (lane >> 2);
                int cc = kb + (lane & 3);
                af[mt][0] = As[r][cc];
                af[mt][1] = As[r + 8][cc];
                af[mt][2] = As[r][cc + 4];
                af[mt][3] = As[r + 8][cc + 4];
            }
#pragma unroll
            for (int nt = 0; nt < 4; nt++) {
                int n = wn + nt * 8 + (lane >> 2);
                int k = kb + (lane & 3);
                bf[nt][0] = Bs[n][k];
                bf[nt][1] = Bs[n][k + 4];
            }
#pragma unroll
            for (int mt = 0; mt < 2; mt++)
#pragma unroll
                for (int nt = 0; nt < 4; nt++) mma8(acc[mt][nt], af[mt], bf[nt]);
        }
    }

    // ---- epilogue ----
    const int sec = blockIdx.x;  // gate section for EPI 0
#pragma unroll
    for (int mt = 0; mt < 2; mt++) {
#pragma unroll
        for (int nt = 0; nt < 4; nt++) {
            int colb = wn + nt * 8 + 2 * (lane & 3);
            int r0 = m0 + wm + mt * 16 + (lane >> 2);
            int r1 = r0 + 8;
            float2 v0 = make_float2(acc[mt][nt][0], acc[mt][nt][1]);
            float2 v1 = make_float2(acc[mt][nt][2], acc[mt][nt][3]);
            if (EPI == 0) {
                if (sec == 0) {
                    float2 b = *(const float2*)(g_bc1 + colb);
                    float2 o0 = make_float2(sigf(v0.x + b.x), sigf(v0.y + b.y));
                    float2 o1 = make_float2(sigf(v1.x + b.x), sigf(v1.y + b.y));
                    *(float2*)(g_Z + (size_t)r0 * 64 + colb) = o0;
                    *(float2*)(g_Z + (size_t)r1 * 64 + colb) = o1;
                } else if (sec == 1) {
                    float2 b = *(const float2*)(g_bc1 + 64 + colb);
                    float2 h0 = *(const float2*)(g_Hst + (size_t)r0 * 64 + colb);
                    float2 h1 = *(const float2*)(g_Hst + (size_t)r1 * 64 + colb);
                    float2 o0 = make_float2(h0.x * sigf(v0.x + b.x), h0.y * sigf(v0.y + b.y));
                    float2 o1 = make_float2(h1.x * sigf(v1.x + b.x), h1.y * sigf(v1.y + b.y));
                    *(float2*)(g_HR + (size_t)r0 * 64 + colb) = o0;
                    *(float2*)(g_HR + (size_t)r1 * 64 + colb) = o1;
                } else {
                    float2 b = *(const float2*)(g_bc1 + 128 + colb);
                    float2 o0 = make_float2(v0.x + b.x, v0.y + b.y);
                    float2 o1 = make_float2(v1.x + b.x, v1.y + b.y);
                    *(float2*)(g_Gxh + (size_t)r0 * 64 + colb) = o0;
                    *(float2*)(g_Gxh + (size_t)r1 * 64 + colb) = o1;
                }
            } else if (EPI == 1) {
                float2 b = make_float2(a.bias[colb], a.bias[colb + 1]);
                float2 g0 = *(const float2*)(g_Gxh + (size_t)r0 * 64 + colb);
                float2 g1 = *(const float2*)(g_Gxh + (size_t)r1 * 64 + colb);
                float2 z0 = *(const float2*)(g_Z + (size_t)r0 * 64 + colb);
                float2 z1 = *(const float2*)(g_Z + (size_t)r1 * 64 + colb);
                float2 h0 = *(const float2*)(g_Hst + (size_t)r0 * 64 + colb);
                float2 h1 = *(const float2*)(g_Hst + (size_t)r1 * 64 + colb);
                float t0x = tanhf(v0.x + g0.x + b.x), t0y = tanhf(v0.y + g0.y + b.y);
                float t1x = tanhf(v1.x + g1.x + b.x), t1y = tanhf(v1.y + g1.y + b.y);
                float2 o0 = make_float2(fmaxf(z0.x * h0.x + (1.f - z0.x) * t0x, 0.f),
                                        fmaxf(z0.y * h0.y + (1.f - z0.y) * t0y, 0.f));
                float2 o1 = make_float2(fmaxf(z1.x * h1.x + (1.f - z1.x) * t1x, 0.f),
                                        fmaxf(z1.y * h1.y + (1.f - z1.y) * t1y, 0.f));
                *(float2*)(g_Hst + (size_t)r0 * 64 + colb) = o0;
                *(float2*)(g_Hst + (size_t)r1 * 64 + colb) = o1;
            } else {
                float2 b = make_float2(a.bias[n0 + colb], a.bias[n0 + colb + 1]);
                float2 o0 = make_float2(fmaxf(v0.x + b.x, 0.f), fmaxf(v0.y + b.y, 0.f));
                float2 o1 = make_float2(fmaxf(v1.x + b.x, 0.f), fmaxf(v1.y + b.y, 0.f));
                *(float2*)(a.C + (size_t)r0 * a.ldc + n0 + colb) = o0;
                *(float2*)(a.C + (size_t)r1 * a.ldc + n0 + colb) = o1;
            }
        }
    }
}

// ---------------- final layer + softmax ----------------
__global__ void k_out(const float* __restrict__ A, const float* __restrict__ W3,
                      const float* __restrict__ b3, float* __restrict__ out) {
    int warp = threadIdx.x >> 5, lane = threadIdx.x & 31;
    int row = blockIdx.x * 8 + warp;
    float s0 = 0.f, s1 = 0.f;
    for (int k = lane; k < 320; k += 32) {
        float a = A[row * 320 + k];
        s0 += a * W3[k * 2];
        s1 += a * W3[k * 2 + 1];
    }
#pragma unroll
    for (int o = 16; o; o >>= 1) {
        s0 += __shfl_xor_sync(0xffffffffu, s0, o);
        s1 += __shfl_xor_sync(0xffffffffu, s1, o);
    }
    if (lane == 0) {
        float l0 = s0 + b3[0], l1 = s1 + b3[1];
        float m = fmaxf(l0, l1);
        float e0 = expf(l0 - m), e1 = expf(l1 - m);
        float inv = 1.f / (e0 + e1);
        out[row * 2] = e0 * inv;
        out[row * 2 + 1] = e1 * inv;
    }
}

// ---------------- launch ----------------
extern "C" void kernel_launch(void* const* d_in, const int* in_sizes, int n_in,
                              void* d_out, int out_size) {
    const float* x = (const float*)d_in[0];
    const int* ei = (const int*)d_in[1];
    const float* ew = (const float*)d_in[2];
    const float* Wxz = (const float*)d_in[3];  const float* bxz = (const float*)d_in[4];
    const float* Whz = (const float*)d_in[5];  const float* bhz = (const float*)d_in[6];
    const float* Wxr = (const float*)d_in[7];  const float* bxr = (const float*)d_in[8];
    const float* Whr = (const float*)d_in[9];  const float* bhr = (const float*)d_in[10];
    const float* Wxh = (const float*)d_in[11]; const float* bxh = (const float*)d_in[12];
    const float* Whh = (const float*)d_in[13]; const float* bhh = (const float*)d_in[14];
    const float* W1 = (const float*)d_in[15];  const float* b1 = (const float*)d_in[16];
    const float* W2 = (const float*)d_in[17];  const float* b2 = (const float*)d_in[18];
    const float* W3 = (const float*)d_in[19];  const float* b3 = (const float*)d_in[20];
    float* out = (float*)d_out;
    const int* src = ei;
    const int* dst = ei + NEDGE;

    float *pDeg, *pP1, *pP2, *pP3, *pP4, *pHR, *pH;
    float *pWB1, *pWB2, *pWB3, *pWB4, *pM1, *pM2;
    int* pFill;
    cudaGetSymbolAddress((void**)&pDeg, g_deg);
    cudaGetSymbolAddress((void**)&pFill, g_fill);
    cudaGetSymbolAddress((void**)&pP1, g_P1);
    cudaGetSymbolAddress((void**)&pP2, g_P2);
    cudaGetSymbolAddress((void**)&pP3, g_P3);
    cudaGetSymbolAddress((void**)&pP4, g_P4);
    cudaGetSymbolAddress((void**)&pHR, g_HR);
    cudaGetSymbolAddress((void**)&pH, g_Hst);
    cudaGetSymbolAddress((void**)&pWB1, g_WB1);
    cudaGetSymbolAddress((void**)&pWB2, g_WB2);
    cudaGetSymbolAddress((void**)&pWB3, g_WB3);
    cudaGetSymbolAddress((void**)&pWB4, g_WB4);
    cudaGetSymbolAddress((void**)&pM1, g_M1);
    cudaGetSymbolAddress((void**)&pM2, g_M2);

    // ---- preprocessing ----
    cudaMemsetAsync(pDeg, 0, BNN * sizeof(float));
    cudaMemsetAsync(pFill, 0, BNN * sizeof(int));
    cudaMemsetAsync(pH, 0, (size_t)BNN * 64 * sizeof(float));
    k_degcnt<<<NEDGE / 256, 256>>>(src, dst, ew);
    k_dinv<<<BNN / 256, 256>>>();
    k_scanA<<<80, 1024>>>();
    k_scanB<<<1, 32>>>();
    k_scanC<<<80, 1024>>>();
    k_fillcsr<<<NEDGE / 256, 256>>>(src, dst, ew);
    k_packW<<<(1110208 + 255) / 256, 256>>>(Wxz, Wxr, Wxh, Whz, Whr, Whh,
                                            bxz, bxr, bxh, bhz, bhr, W1, W2);

    const int pg = BNN * 16 / 128;  // 10240

    Args a1{};  // fused gate GEMM (K=384, N=192)
    a1.nk = 12; a1.ktot = 384; a1.B = pWB1;
    Args a2{};  // hh GEMM + GRU update (K=192, N=64)
    a2.nk = 6; a2.ktot = 192; a2.B = pWB2; a2.bias = bhh;

    for (int t = 0; t < NT; t++) {
        const float* Xt = x + (size_t)t * BNN * 64;
        k_prop<<<pg, 128>>>((const float4*)Xt, (float4*)pP1, 1.f, nullptr, 0.f);
        k_prop<<<pg, 128>>>((const float4*)pP1, (float4*)pP2, 2.f, (const float4*)Xt, -1.f);
        k_prop<<<pg, 128>>>((const float4*)pH, (float4*)pP3, 1.f, nullptr, 0.f);
        k_prop<<<pg, 128>>>((const float4*)pP3, (float4*)pP4, 2.f, (const float4*)pH, -1.f);
        a1.a0 = Xt; a1.a1 = pP1; a1.a2 = pP2; a1.a3 = pH; a1.a4 = pP3; a1.a5 = pP4;
        k_mma<0, true><<<dim3(3, 640), 256>>>(a1);
        k_prop<<<pg, 128>>>((const float4*)pHR, (float4*)pP1, 1.f, nullptr, 0.f);
        k_prop<<<pg, 128>>>((const float4*)pP1, (float4*)pP2, 2.f, (const float4*)pHR, -1.f);
        a2.a0 = pHR; a2.a1 = pP1; a2.a2 = pP2;
        k_mma<1, true><<<dim3(1, 640), 256>>>(a2);
    }

    // ---- MLP head: H as [4096, 1280] ----
    Args m1{}; m1.a0 = pH; m1.astride = 1280; m1.nk = 40; m1.ktot = 1280;
    m1.B = pWB3; m1.bias = b1; m1.C = pM1; m1.ldc = 640;
    k_mma<2, false><<<dim3(10, 32), 256>>>(m1);
    Args m2{}; m2.a0 = pM1; m2.astride = 640; m2.nk = 20; m2.ktot = 640;
    m2.B = pWB4; m2.bias = b2; m2.C = pM2; m2.ldc = 320;
    k_mma<2, false><<<dim3(5, 32), 256>>>(m2);
    k_out<<<512, 256>>>(pM2, W3, b3, out);
}

// round 9
// speedup vs baseline: 2.2766x; 1.5295x over previous
#include <cuda_runtime.h>
#include <math.h>
#include <stdint.h>

#define BNN   81920
#define NEDGE 327680
#define NT    16
#define MT    (NT * BNN)   // 1310720 rows across all timesteps

// ---------------- static device scratch ----------------
__device__ __align__(256) float g_deg[BNN];
__device__ __align__(256) float g_dinv[BNN];
__device__ __align__(256) int   g_rowptr[BNN + 1];
__device__ __align__(256) int   g_fill[BNN];
__device__ __align__(256) int   g_bsum[80];
__device__ __align__(256) int   g_boff[80];
__device__ __align__(256) int   g_csr_src[NEDGE];
__device__ __align__(256) float g_csr_w[NEDGE];
__device__ __align__(256) float g_P1a[(size_t)MT * 64];  // L*X all t
__device__ __align__(256) float g_P2a[(size_t)MT * 64];  // T2(X) all t
__device__ __align__(256) float g_GxA[(size_t)MT * 192]; // X-side gate pre-acts, all t
__device__ __align__(256) float g_P3[BNN * 64];
__device__ __align__(256) float g_P4[BNN * 64];
__device__ __align__(256) float g_Z[BNN * 64];
__device__ __align__(256) float g_HR[BNN * 64];
__device__ __align__(256) float g_Hst[BNN * 64];
__device__ __align__(256) float g_WBx[192 * 192];   // [N][K] X gates z|r|h
__device__ __align__(256) float g_WBh[128 * 192];   // [N][K] H gates z|r
__device__ __align__(256) float g_WB2[64 * 192];    // [N][K] hh
__device__ __align__(256) float g_WB3[640 * 1280];  // W1^T
__device__ __align__(256) float g_WB4[320 * 640];   // W2^T
__device__ __align__(256) float g_bc1[192];         // summed gate biases z|r|h
__device__ __align__(256) float g_M1[4096 * 640];
__device__ __align__(256) float g_M2[4096 * 320];

// ---------------- helpers ----------------
__device__ __forceinline__ uint32_t f2tf(float f) {
    uint32_t r;
    asm("cvt.rna.tf32.f32 %0, %1;" : "=r"(r) : "f"(f));
    return r;
}
__device__ __forceinline__ void mma8(float* d, const uint32_t* a, const uint32_t* b) {
    asm volatile(
        "mma.sync.aligned.m16n8k8.row.col.f32.tf32.tf32.f32 "
        "{%0,%1,%2,%3}, {%4,%5,%6,%7}, {%8,%9}, {%0,%1,%2,%3};"
        : "+f"(d[0]), "+f"(d[1]), "+f"(d[2]), "+f"(d[3])
        : "r"(a[0]), "r"(a[1]), "r"(a[2]), "r"(a[3]), "r"(b[0]), "r"(b[1]));
}
__device__ __forceinline__ float sigf(float x) { return 1.f / (1.f + expf(-x)); }

// ---------------- graph preprocessing ----------------
__global__ void k_degcnt(const int* __restrict__ src, const int* __restrict__ dst,
                         const float* __restrict__ w) {
    int e = blockIdx.x * 256 + threadIdx.x;
    atomicAdd(&g_deg[src[e]], w[e]);
    atomicAdd(&g_fill[dst[e]], 1);
}
__global__ void k_dinv() {
    int n = blockIdx.x * 256 + threadIdx.x;
    float d = g_deg[n];
    g_dinv[n] = (d > 0.f) ? rsqrtf(d) : 0.f;
}
__global__ void k_scanA() {  // 80 x 1024
    int tid = threadIdx.x, lane = tid & 31, wp = tid >> 5, b = blockIdx.x;
    __shared__ int wsum[32];
    int v = g_fill[b * 1024 + tid], x = v;
#pragma unroll
    for (int o = 1; o < 32; o <<= 1) {
        int n = __shfl_up_sync(0xffffffffu, x, o);
        if (lane >= o) x += n;
    }
    if (lane == 31) wsum[wp] = x;
    __syncthreads();
    if (wp == 0) {
        int y = wsum[lane];
#pragma unroll
        for (int o = 1; o < 32; o <<= 1) {
            int n = __shfl_up_sync(0xffffffffu, y, o);
            if (lane >= o) y += n;
        }
        wsum[lane] = y;
    }
    __syncthreads();
    int base = (wp > 0) ? wsum[wp - 1] : 0;
    g_rowptr[b * 1024 + tid] = base + x - v;
    if (tid == 1023) g_bsum[b] = base + x;
}
__global__ void k_scanB() {  // 1 x 32
    int lane = threadIdx.x;
    int carry = 0;
    for (int base = 0; base < 80; base += 32) {
        int v = (base + lane < 80) ? g_bsum[base + lane] : 0, x = v;
#pragma unroll
        for (int o = 1; o < 32; o <<= 1) {
            int n = __shfl_up_sync(0xffffffffu, x, o);
            if (lane >= o) x += n;
        }
        if (base + lane < 80) g_boff[base + lane] = carry + x - v;
        carry += __shfl_sync(0xffffffffu, x, 31);
    }
    if (lane == 0) g_rowptr[BNN] = carry;
}
__global__ void k_scanC() {  // 80 x 1024
    int i = blockIdx.x * 1024 + threadIdx.x;
    int r = g_rowptr[i] + g_boff[blockIdx.x];
    g_rowptr[i] = r;
    g_fill[i] = r;
}
__global__ void k_fillcsr(const int* __restrict__ src, const int* __restrict__ dst,
                          const float* __restrict__ w) {
    int e = blockIdx.x * 256 + threadIdx.x;
    int s = src[e], d = dst[e];
    float wn = -g_dinv[s] * w[e] * g_dinv[d];
    int pos = atomicAdd(&g_fill[d], 1);
    g_csr_src[pos] = s;
    g_csr_w[pos] = wn;
}

// ---------------- weight packing (B stored [N][K] row-major) ----------------
__global__ void k_packW(const float* __restrict__ Wxz, const float* __restrict__ Wxr,
                        const float* __restrict__ Wxh, const float* __restrict__ Whz,
                        const float* __restrict__ Whr, const float* __restrict__ Whh,
                        const float* __restrict__ bxz, const float* __restrict__ bxr,
                        const float* __restrict__ bxh, const float* __restrict__ bhz,
                        const float* __restrict__ bhr, const float* __restrict__ bhh,
                        const float* __restrict__ W1, const float* __restrict__ W2) {
    int idx = blockIdx.x * 256 + threadIdx.x;
    if (idx < 36864) {  // WBx [192][192]
        int n = idx / 192, k = idx % 192, kb = k >> 6, j = k & 63;
        const float* W = (n < 64) ? Wxz : ((n < 128) ? Wxr : Wxh);
        g_WBx[idx] = W[kb * 4096 + j * 64 + (n & 63)];
    } else if (idx < 61440) {  // WBh [128][192]
        int t = idx - 36864;
        int n = t / 192, k = t % 192, kb = k >> 6, j = k & 63;
        const float* W = (n < 64) ? Whz : Whr;
        g_WBh[t] = W[kb * 4096 + j * 64 + (n & 63)];
    } else if (idx < 73728) {  // WB2 [64][192]
        int t = idx - 61440;
        int n = t / 192, k = t % 192, kb = k >> 6, j = k & 63;
        g_WB2[t] = Whh[kb * 4096 + j * 64 + n];
    } else if (idx < 892928) {  // WB3 [640][1280] = W1^T
        int t = idx - 73728;
        int n = t / 1280, k = t % 1280;
        g_WB3[t] = W1[k * 640 + n];
    } else if (idx < 1097728) {  // WB4 [320][640] = W2^T
        int t = idx - 892928;
        int n = t / 640, k = t % 640;
        g_WB4[t] = W2[k * 320 + n];
    } else if (idx < 1097920) {
        int c = idx - 1097728;
        float v;
        if (c < 64) v = bxz[c] + bhz[c];
        else if (c < 128) v = bxr[c - 64] + bhr[c - 64];
        else v = bxh[c - 128] + bhh[c - 128];
        g_bc1[c] = v;
    }
}

// ---------------- sparse propagation (grid.y = timestep offset) ----------------
__global__ void k_prop(const float4* __restrict__ X, float4* __restrict__ out,
                       float alpha, const float4* __restrict__ base, float beta) {
    size_t toff = (size_t)blockIdx.y * (BNN * 16);
    int i = blockIdx.x * 128 + threadIdx.x;
    int node = i >> 4, l = i & 15;
    X += toff; out += toff;
    int s = g_rowptr[node], e = g_rowptr[node + 1];
    float ax = 0.f, ay = 0.f, az = 0.f, aw = 0.f;
    for (int k = s; k < e; k++) {
        int sc = g_csr_src[k];
        float w = g_csr_w[k];
        float4 v = X[sc * 16 + l];
        ax += w * v.x; ay += w * v.y; az += w * v.z; aw += w * v.w;
    }
    float4 r;
    r.x = alpha * ax; r.y = alpha * ay; r.z = alpha * az; r.w = alpha * aw;
    if (beta != 0.f) {
        float4 b = (base + toff)[node * 16 + l];
        r.x += beta * b.x; r.y += beta * b.y; r.z += beta * b.z; r.w += beta * b.w;
    }
    out[node * 16 + l] = r;
}

// ---------------- tf32 mma.sync GEMM: block 128x64, 8 warps ----------------
// C = A @ B^T, B stored [N][K].  EPI 0: H-gate epilogue (sec 0: Z, sec 1: HR).
// EPI 1: GRU update -> H.  EPI 2: relu(v + bias) -> C.  EPI 3: raw v -> C.
struct Args {
    const float* a0; const float* a1; const float* a2;
    int astride; int nk; int ktot;
    const float* B; const float* bias;
    float* C; int ldc;
    const float* G;   // per-step X-side gate slice [row][192]
};

template <int EPI, bool MULTI>
__global__ __launch_bounds__(256) void k_mma(Args a) {
    __shared__ uint32_t As[128][36];
    __shared__ uint32_t Bs[64][36];
    const int tid = threadIdx.x, wid = tid >> 5, lane = tid & 31;
    const int wm = (wid & 3) * 32, wn = (wid >> 2) * 32;
    const int m0 = blockIdx.y * 128, n0 = blockIdx.x * 64;

    float acc[2][4][4];
#pragma unroll
    for (int i = 0; i < 2; i++)
#pragma unroll
        for (int j = 0; j < 4; j++)
#pragma unroll
            for (int q = 0; q < 4; q++) acc[i][j][q] = 0.f;

    const int arow = tid >> 1, acb = (tid & 1) * 16;
    const int brow = tid >> 2, bcb = (tid & 3) * 8;

    for (int c = 0; c < a.nk; c++) {
        const float* Ap;
        int koff, rs;
        if (MULTI) {
            int sel = c >> 1;
            Ap = (sel == 0) ? a.a0 : (sel == 1) ? a.a1 : a.a2;
            koff = (c & 1) * 32;
            rs = 64;
        } else {
            Ap = a.a0; koff = c * 32; rs = a.astride;
        }
        __syncthreads();
        {
            const float* rp = Ap + (size_t)(m0 + arow) * rs + koff + acb;
#pragma unroll
            for (int j = 0; j < 4; j++) {
                float4 v = *(const float4*)(rp + j * 4);
                As[arow][acb + j * 4 + 0] = f2tf(v.x);
                As[arow][acb + j * 4 + 1] = f2tf(v.y);
                As[arow][acb + j * 4 + 2] = f2tf(v.z);
                As[arow][acb + j * 4 + 3] = f2tf(v.w);
            }
        }
        {
            const float* rp = a.B + (size_t)(n0 + brow) * a.ktot + c * 32 + bcb;
#pragma unroll
            for (int j = 0; j < 2; j++) {
                float4 v = *(const float4*)(rp + j * 4);
                Bs[brow][bcb + j * 4 + 0] = f2tf(v.x);
                Bs[brow][bcb + j * 4 + 1] = f2tf(v.y);
                Bs[brow][bcb + j * 4 + 2] = f2tf(v.z);
                Bs[brow][bcb + j * 4 + 3] = f2tf(v.w);
            }
        }
        __syncthreads();
#pragma unroll
        for (int ks = 0; ks < 4; ks++) {
            const int kb = ks * 8;
            uint32_t af[2][4], bf[4][2];
#pragma unroll
            for (int mt = 0; mt < 2; mt++) {
                int r = wm + mt * 16 + (lane >> 2);
                int cc = kb + (lane & 3);
                af[mt][0] = As[r][cc];
                af[mt][1] = As[r + 8][cc];
                af[mt][2] = As[r][cc + 4];
                af[mt][3] = As[r + 8][cc + 4];
            }
#pragma unroll
            for (int nt = 0; nt < 4; nt++) {
                int n = wn + nt * 8 + (lane >> 2);
                int k = kb + (lane & 3);
                bf[nt][0] = Bs[n][k];
                bf[nt][1] = Bs[n][k + 4];
            }
#pragma unroll
            for (int mt = 0; mt < 2; mt++)
#pragma unroll
                for (int nt = 0; nt < 4; nt++) mma8(acc[mt][nt], af[mt], bf[nt]);
        }
    }

    const int sec = blockIdx.x;
#pragma unroll
    for (int mt = 0; mt < 2; mt++) {
#pragma unroll
        for (int nt = 0; nt < 4; nt++) {
            int colb = wn + nt * 8 + 2 * (lane & 3);
            int r0 = m0 + wm + mt * 16 + (lane >> 2);
            int r1 = r0 + 8;
            float2 v0 = make_float2(acc[mt][nt][0], acc[mt][nt][1]);
            float2 v1 = make_float2(acc[mt][nt][2], acc[mt][nt][3]);
            if (EPI == 0) {
                float2 g0 = *(const float2*)(a.G + (size_t)r0 * 192 + sec * 64 + colb);
                float2 g1 = *(const float2*)(a.G + (size_t)r1 * 192 + sec * 64 + colb);
                float2 b = *(const float2*)(g_bc1 + sec * 64 + colb);
                if (sec == 0) {  // Z
                    float2 o0 = make_float2(sigf(v0.x + g0.x + b.x), sigf(v0.y + g0.y + b.y));
                    float2 o1 = make_float2(sigf(v1.x + g1.x + b.x), sigf(v1.y + g1.y + b.y));
                    *(float2*)(g_Z + (size_t)r0 * 64 + colb) = o0;
                    *(float2*)(g_Z + (size_t)r1 * 64 + colb) = o1;
                } else {  // HR = H * R
                    float2 h0 = *(const float2*)(g_Hst + (size_t)r0 * 64 + colb);
                    float2 h1 = *(const float2*)(g_Hst + (size_t)r1 * 64 + colb);
                    float2 o0 = make_float2(h0.x * sigf(v0.x + g0.x + b.x),
                                            h0.y * sigf(v0.y + g0.y + b.y));
                    float2 o1 = make_float2(h1.x * sigf(v1.x + g1.x + b.x),
                                            h1.y * sigf(v1.y + g1.y + b.y));
                    *(float2*)(g_HR + (size_t)r0 * 64 + colb) = o0;
                    *(float2*)(g_HR + (size_t)r1 * 64 + colb) = o1;
                }
            } else if (EPI == 1) {  // H = relu(Z*H + (1-Z)*tanh(v + Gx_h + b_h))
                float2 g0 = *(const float2*)(a.G + (size_t)r0 * 192 + 128 + colb);
                float2 g1 = *(const float2*)(a.G + (size_t)r1 * 192 + 128 + colb);
                float2 b = *(const float2*)(g_bc1 + 128 + colb);
                float2 z0 = *(const float2*)(g_Z + (size_t)r0 * 64 + colb);
                float2 z1 = *(const float2*)(g_Z + (size_t)r1 * 64 + colb);
                float2 h0 = *(const float2*)(g_Hst + (size_t)r0 * 64 + colb);
                float2 h1 = *(const float2*)(g_Hst + (size_t)r1 * 64 + colb);
                float t0x = tanhf(v0.x + g0.x + b.x), t0y = tanhf(v0.y + g0.y + b.y);
                float t1x = tanhf(v1.x + g1.x + b.x), t1y = tanhf(v1.y + g1.y + b.y);
                float2 o0 = make_float2(fmaxf(z0.x * h0.x + (1.f - z0.x) * t0x, 0.f),
                                        fmaxf(z0.y * h0.y + (1.f - z0.y) * t0y, 0.f));
                float2 o1 = make_float2(fmaxf(z1.x * h1.x + (1.f - z1.x) * t1x, 0.f),
                                        fmaxf(z1.y * h1.y + (1.f - z1.y) * t1y, 0.f));
                *(float2*)(g_Hst + (size_t)r0 * 64 + colb) = o0;
                *(float2*)(g_Hst + (size_t)r1 * 64 + colb) = o1;
            } else if (EPI == 2) {
                float2 b = make_float2(a.bias[n0 + colb], a.bias[n0 + colb + 1]);
                float2 o0 = make_float2(fmaxf(v0.x + b.x, 0.f), fmaxf(v0.y + b.y, 0.f));
                float2 o1 = make_float2(fmaxf(v1.x + b.x, 0.f), fmaxf(v1.y + b.y, 0.f));
                *(float2*)(a.C + (size_t)r0 * a.ldc + n0 + colb) = o0;
                *(float2*)(a.C + (size_t)r1 * a.ldc + n0 + colb) = o1;
            } else {  // raw store
                *(float2*)(a.C + (size_t)r0 * a.ldc + n0 + colb) = v0;
                *(float2*)(a.C + (size_t)r1 * a.ldc + n0 + colb) = v1;
            }
        }
    }
}

// ---------------- t = 0 special case (H0 = 0) ----------------
__global__ void k_step0(const float* __restrict__ G) {
    int i = blockIdx.x * 256 + threadIdx.x;  // over BNN*64
    int r = i >> 6, c = i & 63;
    float z = sigf(G[(size_t)r * 192 + c] + g_bc1[c]);
    float ht = tanhf(G[(size_t)r * 192 + 128 + c] + g_bc1[128 + c]);
    g_Hst[i] = fmaxf((1.f - z) * ht, 0.f);
}

// ---------------- final layer + softmax ----------------
__global__ void k_out(const float* __restrict__ A, const float* __restrict__ W3,
                      const float* __restrict__ b3, float* __restrict__ out) {
    int warp = threadIdx.x >> 5, lane = threadIdx.x & 31;
    int row = blockIdx.x * 8 + warp;
    float s0 = 0.f, s1 = 0.f;
    for (int k = lane; k < 320; k += 32) {
        float a = A[row * 320 + k];
        s0 += a * W3[k * 2];
        s1 += a * W3[k * 2 + 1];
    }
#pragma unroll
    for (int o = 16; o; o >>= 1) {
        s0 += __shfl_xor_sync(0xffffffffu, s0, o);
        s1 += __shfl_xor_sync(0xffffffffu, s1, o);
    }
    if (lane == 0) {
        float l0 = s0 + b3[0], l1 = s1 + b3[1];
        float m = fmaxf(l0, l1);
        float e0 = expf(l0 - m), e1 = expf(l1 - m);
        float inv = 1.f / (e0 + e1);
        out[row * 2] = e0 * inv;
        out[row * 2 + 1] = e1 * inv;
    }
}

// ---------------- launch ----------------
extern "C" void kernel_launch(void* const* d_in, const int* in_sizes, int n_in,
                              void* d_out, int out_size) {
    const float* x = (const float*)d_in[0];
    const int* ei = (const int*)d_in[1];
    const float* ew = (const float*)d_in[2];
    const float* Wxz = (const float*)d_in[3];  const float* bxz = (const float*)d_in[4];
    const float* Whz = (const float*)d_in[5];  const float* bhz = (const float*)d_in[6];
    const float* Wxr = (const float*)d_in[7];  const float* bxr = (const float*)d_in[8];
    const float* Whr = (const float*)d_in[9];  const float* bhr = (const float*)d_in[10];
    const float* Wxh = (const float*)d_in[11]; const float* bxh = (const float*)d_in[12];
    const float* Whh = (const float*)d_in[13]; const float* bhh = (const float*)d_in[14];
    const float* W1 = (const float*)d_in[15];  const float* b1 = (const float*)d_in[16];
    const float* W2 = (const float*)d_in[17];  const float* b2 = (const float*)d_in[18];
    const float* W3 = (const float*)d_in[19];  const float* b3 = (const float*)d_in[20];
    float* out = (float*)d_out;
    const int* src = ei;
    const int* dst = ei + NEDGE;

    float *pDeg, *pP1a, *pP2a, *pGxA, *pP3, *pP4, *pHR, *pH;
    float *pWBx, *pWBh, *pWB2, *pWB3, *pWB4, *pM1, *pM2;
    int* pFill;
    cudaGetSymbolAddress((void**)&pDeg, g_deg);
    cudaGetSymbolAddress((void**)&pFill, g_fill);
    cudaGetSymbolAddress((void**)&pP1a, g_P1a);
    cudaGetSymbolAddress((void**)&pP2a, g_P2a);
    cudaGetSymbolAddress((void**)&pGxA, g_GxA);
    cudaGetSymbolAddress((void**)&pP3, g_P3);
    cudaGetSymbolAddress((void**)&pP4, g_P4);
    cudaGetSymbolAddress((void**)&pHR, g_HR);
    cudaGetSymbolAddress((void**)&pH, g_Hst);
    cudaGetSymbolAddress((void**)&pWBx, g_WBx);
    cudaGetSymbolAddress((void**)&pWBh, g_WBh);
    cudaGetSymbolAddress((void**)&pWB2, g_WB2);
    cudaGetSymbolAddress((void**)&pWB3, g_WB3);
    cudaGetSymbolAddress((void**)&pWB4, g_WB4);
    cudaGetSymbolAddress((void**)&pM1, g_M1);
    cudaGetSymbolAddress((void**)&pM2, g_M2);

    // ---- preprocessing ----
    cudaMemsetAsync(pDeg, 0, BNN * sizeof(float));
    cudaMemsetAsync(pFill, 0, BNN * sizeof(int));
    k_degcnt<<<NEDGE / 256, 256>>>(src, dst, ew);
    k_dinv<<<BNN / 256, 256>>>();
    k_scanA<<<80, 1024>>>();
    k_scanB<<<1, 32>>>();
    k_scanC<<<80, 1024>>>();
    k_fillcsr<<<NEDGE / 256, 256>>>(src, dst, ew);
    k_packW<<<(1097920 + 255) / 256, 256>>>(Wxz, Wxr, Wxh, Whz, Whr, Whh,
                                            bxz, bxr, bxh, bhz, bhr, bhh, W1, W2);

    const dim3 pgAll(BNN * 16 / 128, NT);  // all timesteps at once
    const dim3 pg1(BNN * 16 / 128, 1);

    // ---- X-side, hoisted out of the recurrence ----
    k_prop<<<pgAll, 128>>>((const float4*)x, (float4*)pP1a, 1.f, nullptr, 0.f);
    k_prop<<<pgAll, 128>>>((const float4*)pP1a, (float4*)pP2a, 2.f, (const float4*)x, -1.f);
    Args ax{};
    ax.a0 = x; ax.a1 = pP1a; ax.a2 = pP2a; ax.nk = 6; ax.ktot = 192;
    ax.B = pWBx; ax.C = pGxA; ax.ldc = 192;
    k_mma<3, true><<<dim3(3, MT / 128), 256>>>(ax);

    // ---- recurrence ----
    k_step0<<<BNN * 64 / 256, 256>>>(pGxA);

    Args ah{};  // H-gate GEMM (K=192, N=128)
    ah.nk = 6; ah.ktot = 192; ah.B = pWBh;
    Args a2{};  // hh GEMM + GRU update (K=192, N=64)
    a2.nk = 6; a2.ktot = 192; a2.B = pWB2;

    for (int t = 1; t < NT; t++) {
        const float* Gt = pGxA + (size_t)t * BNN * 192;
        k_prop<<<pg1, 128>>>((const float4*)pH, (float4*)pP3, 1.f, nullptr, 0.f);
        k_prop<<<pg1, 128>>>((const float4*)pP3, (float4*)pP4, 2.f, (const float4*)pH, -1.f);
        ah.a0 = pH; ah.a1 = pP3; ah.a2 = pP4; ah.G = Gt;
        k_mma<0, true><<<dim3(2, 640), 256>>>(ah);
        k_prop<<<pg1, 128>>>((const float4*)pHR, (float4*)pP3, 1.f, nullptr, 0.f);
        k_prop<<<pg1, 128>>>((const float4*)pP3, (float4*)pP4, 2.f, (const float4*)pHR, -1.f);
        a2.a0 = pHR; a2.a1 = pP3; a2.a2 = pP4; a2.G = Gt;
        k_mma<1, true><<<dim3(1, 640), 256>>>(a2);
    }

    // ---- MLP head: H as [4096, 1280] ----
    Args m1{}; m1.a0 = pH; m1.astride = 1280; m1.nk = 40; m1.ktot = 1280;
    m1.B = pWB3; m1.bias = b1; m1.C = pM1; m1.ldc = 640;
    k_mma<2, false><<<dim3(10, 32), 256>>>(m1);
    Args m2{}; m2.a0 = pM1; m2.astride = 640; m2.nk = 20; m2.ktot = 640;
    m2.B = pWB4; m2.bias = b2; m2.C = pM2; m2.ldc = 320;
    k_mma<2, false><<<dim3(5, 32), 256>>>(m2);
    k_out<<<512, 256>>>(pM2, W3, b3, out);
}

// round 10
// speedup vs baseline: 2.7110x; 1.1908x over previous
#include <cuda_runtime.h>
#include <math.h>
#include <stdint.h>

#define BNN   81920
#define NEDGE 327680
#define NT    16
#define MT    (NT * BNN)   // 1310720 rows across all timesteps

// ---------------- static device scratch ----------------
__device__ __align__(256) float g_deg[BNN];
__device__ __align__(256) float g_dinv[BNN];
__device__ __align__(256) int   g_rowptr[BNN + 1];
__device__ __align__(256) int   g_fill[BNN];
__device__ __align__(256) int   g_bsum[80];
__device__ __align__(256) int   g_boff[80];
__device__ __align__(256) int   g_csr_src[NEDGE];
__device__ __align__(256) float g_csr_w[NEDGE];
__device__ __align__(256) float g_P1a[(size_t)MT * 64];
__device__ __align__(256) float g_P2a[(size_t)MT * 64];
__device__ __align__(256) float g_GxA[(size_t)MT * 192];
__device__ __align__(256) float g_P3[BNN * 64];
__device__ __align__(256) float g_P4[BNN * 64];
__device__ __align__(256) float g_Z[BNN * 64];
__device__ __align__(256) float g_HR[BNN * 64];
__device__ __align__(256) float g_Hst[BNN * 64];
__device__ __align__(256) float g_WBx[192 * 192];
__device__ __align__(256) float g_WBh[128 * 192];
__device__ __align__(256) float g_WB2[64 * 192];
__device__ __align__(256) float g_WB3[640 * 1280];
__device__ __align__(256) float g_WB4[320 * 640];
__device__ __align__(256) float g_bc1[192];
__device__ __align__(256) float g_M1[4096 * 640];
__device__ __align__(256) float g_M2[4096 * 320];

// ---------------- helpers ----------------
__device__ __forceinline__ uint32_t su32(const void* p) {
    uint32_t a;
    asm("{ .reg .u64 t; cvta.to.shared.u64 t, %1; cvt.u32.u64 %0, t; }" : "=r"(a) : "l"(p));
    return a;
}
__device__ __forceinline__ void cp16(uint32_t dst, const void* src) {
    asm volatile("cp.async.cg.shared.global [%0], [%1], 16;" :: "r"(dst), "l"(src));
}
__device__ __forceinline__ void cp_commit() {
    asm volatile("cp.async.commit_group;" ::: "memory");
}
template <int N>
__device__ __forceinline__ void cp_wait() {
    asm volatile("cp.async.wait_group %0;" :: "n"(N) : "memory");
}
__device__ __forceinline__ void mma8(float* d, const uint32_t* a, const uint32_t* b) {
    asm volatile(
        "mma.sync.aligned.m16n8k8.row.col.f32.tf32.tf32.f32 "
        "{%0,%1,%2,%3}, {%4,%5,%6,%7}, {%8,%9}, {%0,%1,%2,%3};"
        : "+f"(d[0]), "+f"(d[1]), "+f"(d[2]), "+f"(d[3])
        : "r"(a[0]), "r"(a[1]), "r"(a[2]), "r"(a[3]), "r"(b[0]), "r"(b[1]));
}
__device__ __forceinline__ float sigf(float x) { return 1.f / (1.f + expf(-x)); }

// ---------------- graph preprocessing ----------------
__global__ void k_degcnt(const int* __restrict__ src, const int* __restrict__ dst,
                         const float* __restrict__ w) {
    int e = blockIdx.x * 256 + threadIdx.x;
    atomicAdd(&g_deg[src[e]], w[e]);
    atomicAdd(&g_fill[dst[e]], 1);
}
__global__ void k_dinv() {
    int n = blockIdx.x * 256 + threadIdx.x;
    float d = g_deg[n];
    g_dinv[n] = (d > 0.f) ? rsqrtf(d) : 0.f;
}
__global__ void k_scanA() {
    int tid = threadIdx.x, lane = tid & 31, wp = tid >> 5, b = blockIdx.x;
    __shared__ int wsum[32];
    int v = g_fill[b * 1024 + tid], x = v;
#pragma unroll
    for (int o = 1; o < 32; o <<= 1) {
        int n = __shfl_up_sync(0xffffffffu, x, o);
        if (lane >= o) x += n;
    }
    if (lane == 31) wsum[wp] = x;
    __syncthreads();
    if (wp == 0) {
        int y = wsum[lane];
#pragma unroll
        for (int o = 1; o < 32; o <<= 1) {
            int n = __shfl_up_sync(0xffffffffu, y, o);
            if (lane >= o) y += n;
        }
        wsum[lane] = y;
    }
    __syncthreads();
    int base = (wp > 0) ? wsum[wp - 1] : 0;
    g_rowptr[b * 1024 + tid] = base + x - v;
    if (tid == 1023) g_bsum[b] = base + x;
}
__global__ void k_scanB() {
    int lane = threadIdx.x;
    int carry = 0;
    for (int base = 0; base < 80; base += 32) {
        int v = (base + lane < 80) ? g_bsum[base + lane] : 0, x = v;
#pragma unroll
        for (int o = 1; o < 32; o <<= 1) {
            int n = __shfl_up_sync(0xffffffffu, x, o);
            if (lane >= o) x += n;
        }
        if (base + lane < 80) g_boff[base + lane] = carry + x - v;
        carry += __shfl_sync(0xffffffffu, x, 31);
    }
    if (lane == 0) g_rowptr[BNN] = carry;
}
__global__ void k_scanC() {
    int i = blockIdx.x * 1024 + threadIdx.x;
    int r = g_rowptr[i] + g_boff[blockIdx.x];
    g_rowptr[i] = r;
    g_fill[i] = r;
}
__global__ void k_fillcsr(const int* __restrict__ src, const int* __restrict__ dst,
                          const float* __restrict__ w) {
    int e = blockIdx.x * 256 + threadIdx.x;
    int s = src[e], d = dst[e];
    float wn = -g_dinv[s] * w[e] * g_dinv[d];
    int pos = atomicAdd(&g_fill[d], 1);
    g_csr_src[pos] = s;
    g_csr_w[pos] = wn;
}

// ---------------- weight packing ----------------
__global__ void k_packW(const float* __restrict__ Wxz, const float* __restrict__ Wxr,
                        const float* __restrict__ Wxh, const float* __restrict__ Whz,
                        const float* __restrict__ Whr, const float* __restrict__ Whh,
                        const float* __restrict__ bxz, const float* __restrict__ bxr,
                        const float* __restrict__ bxh, const float* __restrict__ bhz,
                        const float* __restrict__ bhr, const float* __restrict__ bhh,
                        const float* __restrict__ W1, const float* __restrict__ W2) {
    int idx = blockIdx.x * 256 + threadIdx.x;
    if (idx < 36864) {
        int n = idx / 192, k = idx % 192, kb = k >> 6, j = k & 63;
        const float* W = (n < 64) ? Wxz : ((n < 128) ? Wxr : Wxh);
        g_WBx[idx] = W[kb * 4096 + j * 64 + (n & 63)];
    } else if (idx < 61440) {
        int t = idx - 36864;
        int n = t / 192, k = t % 192, kb = k >> 6, j = k & 63;
        const float* W = (n < 64) ? Whz : Whr;
        g_WBh[t] = W[kb * 4096 + j * 64 + (n & 63)];
    } else if (idx < 73728) {
        int t = idx - 61440;
        int n = t / 192, k = t % 192, kb = k >> 6, j = k & 63;
        g_WB2[t] = Whh[kb * 4096 + j * 64 + n];
    } else if (idx < 892928) {
        int t = idx - 73728;
        int n = t / 1280, k = t % 1280;
        g_WB3[t] = W1[k * 640 + n];
    } else if (idx < 1097728) {
        int t = idx - 892928;
        int n = t / 640, k = t % 640;
        g_WB4[t] = W2[k * 320 + n];
    } else if (idx < 1097920) {
        int c = idx - 1097728;
        float v;
        if (c < 64) v = bxz[c] + bhz[c];
        else if (c < 128) v = bxr[c - 64] + bhr[c - 64];
        else v = bxh[c - 128] + bhh[c - 128];
        g_bc1[c] = v;
    }
}

// ---------------- sparse propagation ----------------
__global__ void k_prop(const float4* __restrict__ X, float4* __restrict__ out,
                       float alpha, const float4* __restrict__ base, float beta) {
    size_t toff = (size_t)blockIdx.y * (BNN * 16);
    int i = blockIdx.x * 128 + threadIdx.x;
    int node = i >> 4, l = i & 15;
    X += toff; out += toff;
    int s = g_rowptr[node], e = g_rowptr[node + 1];
    float ax = 0.f, ay = 0.f, az = 0.f, aw = 0.f;
    for (int k = s; k < e; k++) {
        int sc = g_csr_src[k];
        float w = g_csr_w[k];
        float4 v = X[sc * 16 + l];
        ax += w * v.x; ay += w * v.y; az += w * v.z; aw += w * v.w;
    }
    float4 r;
    r.x = alpha * ax; r.y = alpha * ay; r.z = alpha * az; r.w = alpha * aw;
    if (beta != 0.f) {
        float4 b = (base + toff)[node * 16 + l];
        r.x += beta * b.x; r.y += beta * b.y; r.z += beta * b.z; r.w += beta * b.w;
    }
    out[node * 16 + l] = r;
}

// ---------------- tf32 mma.sync GEMM, cp.async double-buffered ----------------
// C = A @ B^T, B stored [N][K]. Raw fp32 bits feed mma.tf32 (HW truncation).
// EPI 0: H-gate epilogue (sec 0: Z, sec 1: HR). EPI 1: GRU update -> H.
// EPI 2: relu(v + bias) -> C. EPI 3: raw v -> C.
struct Args {
    const float* a0; const float* a1; const float* a2;
    int astride; int nk; int ktot;
    const float* B; const float* bias;
    float* C; int ldc;
    const float* G;
};

#define AW (128 * 36)
#define BW (64 * 36)

template <int EPI, bool MULTI>
__global__ __launch_bounds__(256) void k_mma(Args a) {
    extern __shared__ uint32_t sm[];
    uint32_t* Asm = sm;             // [2][128][36]
    uint32_t* Bsm = sm + 2 * AW;    // [2][64][36]
    const uint32_t sA = su32(Asm), sB = su32(Bsm);
    const int tid = threadIdx.x, wid = tid >> 5, lane = tid & 31;
    const int wm = (wid & 3) * 32, wn = (wid >> 2) * 32;
    const int m0 = blockIdx.y * 128, n0 = blockIdx.x * 64;

    float acc[2][4][4];
#pragma unroll
    for (int i = 0; i < 2; i++)
#pragma unroll
        for (int j = 0; j < 4; j++)
#pragma unroll
            for (int q = 0; q < 4; q++) acc[i][j][q] = 0.f;

    // issue chunk c into buffer c&1
    auto issue = [&](int c) {
        const float* Ap;
        int koff, rs;
        if (MULTI) {
            int sel = c >> 1;
            Ap = (sel == 0) ? a.a0 : (sel == 1) ? a.a1 : a.a2;
            koff = (c & 1) * 32;
            rs = 64;
        } else {
            Ap = a.a0; koff = c * 32; rs = a.astride;
        }
        const uint32_t abase = sA + (uint32_t)(c & 1) * AW * 4;
        const uint32_t bbase = sB + (uint32_t)(c & 1) * BW * 4;
#pragma unroll
        for (int q = 0; q < 4; q++) {           // A: 1024 16B units
            int u = tid + q * 256;
            int row = u >> 3, j = u & 7;
            cp16(abase + (row * 36 + j * 4) * 4,
                 Ap + (size_t)(m0 + row) * rs + koff + j * 4);
        }
#pragma unroll
        for (int q = 0; q < 2; q++) {           // B: 512 16B units
            int u = tid + q * 256;
            int row = u >> 3, j = u & 7;
            cp16(bbase + (row * 36 + j * 4) * 4,
                 a.B + (size_t)(n0 + row) * a.ktot + c * 32 + j * 4);
        }
        cp_commit();
    };

    issue(0);
    for (int c = 0; c < a.nk; c++) {
        if (c + 1 < a.nk) { issue(c + 1); cp_wait<1>(); }
        else              { cp_wait<0>(); }
        __syncthreads();
        const uint32_t* Ab = Asm + (c & 1) * AW;
        const uint32_t* Bb = Bsm + (c & 1) * BW;
#pragma unroll
        for (int ks = 0; ks < 4; ks++) {
            const int kb = ks * 8;
            uint32_t af[2][4], bf[4][2];
#pragma unroll
            for (int mt = 0; mt < 2; mt++) {
                int r = wm + mt * 16 + (lane >> 2);
                int cc = kb + (lane & 3);
                af[mt][0] = Ab[r * 36 + cc];
                af[mt][1] = Ab[(r + 8) * 36 + cc];
                af[mt][2] = Ab[r * 36 + cc + 4];
                af[mt][3] = Ab[(r + 8) * 36 + cc + 4];
            }
#pragma unroll
            for (int nt = 0; nt < 4; nt++) {
                int n = wn + nt * 8 + (lane >> 2);
                int k = kb + (lane & 3);
                bf[nt][0] = Bb[n * 36 + k];
                bf[nt][1] = Bb[n * 36 + k + 4];
            }
#pragma unroll
            for (int mt = 0; mt < 2; mt++)
#pragma unroll
                for (int nt = 0; nt < 4; nt++) mma8(acc[mt][nt], af[mt], bf[nt]);
        }
        __syncthreads();
    }

    const int sec = blockIdx.x;
#pragma unroll
    for (int mt = 0; mt < 2; mt++) {
#pragma unroll
        for (int nt = 0; nt < 4; nt++) {
            int colb = wn + nt * 8 + 2 * (lane & 3);
            int r0 = m0 + wm + mt * 16 + (lane >> 2);
            int r1 = r0 + 8;
            float2 v0 = make_float2(acc[mt][nt][0], acc[mt][nt][1]);
            float2 v1 = make_float2(acc[mt][nt][2], acc[mt][nt][3]);
            if (EPI == 0) {
                float2 g0 = *(const float2*)(a.G + (size_t)r0 * 192 + sec * 64 + colb);
                float2 g1 = *(const float2*)(a.G + (size_t)r1 * 192 + sec * 64 + colb);
                float2 b = *(const float2*)(g_bc1 + sec * 64 + colb);
                if (sec == 0) {
                    float2 o0 = make_float2(sigf(v0.x + g0.x + b.x), sigf(v0.y + g0.y + b.y));
                    float2 o1 = make_float2(sigf(v1.x + g1.x + b.x), sigf(v1.y + g1.y + b.y));
                    *(float2*)(g_Z + (size_t)r0 * 64 + colb) = o0;
                    *(float2*)(g_Z + (size_t)r1 * 64 + colb) = o1;
                } else {
                    float2 h0 = *(const float2*)(g_Hst + (size_t)r0 * 64 + colb);
                    float2 h1 = *(const float2*)(g_Hst + (size_t)r1 * 64 + colb);
                    float2 o0 = make_float2(h0.x * sigf(v0.x + g0.x + b.x),
                                            h0.y * sigf(v0.y + g0.y + b.y));
                    float2 o1 = make_float2(h1.x * sigf(v1.x + g1.x + b.x),
                                            h1.y * sigf(v1.y + g1.y + b.y));
                    *(float2*)(g_HR + (size_t)r0 * 64 + colb) = o0;
                    *(float2*)(g_HR + (size_t)r1 * 64 + colb) = o1;
                }
            } else if (EPI == 1) {
                float2 g0 = *(const float2*)(a.G + (size_t)r0 * 192 + 128 + colb);
                float2 g1 = *(const float2*)(a.G + (size_t)r1 * 192 + 128 + colb);
                float2 b = *(const float2*)(g_bc1 + 128 + colb);
                float2 z0 = *(const float2*)(g_Z + (size_t)r0 * 64 + colb);
                float2 z1 = *(const float2*)(g_Z + (size_t)r1 * 64 + colb);
                float2 h0 = *(const float2*)(g_Hst + (size_t)r0 * 64 + colb);
                float2 h1 = *(const float2*)(g_Hst + (size_t)r1 * 64 + colb);
                float t0x = tanhf(v0.x + g0.x + b.x), t0y = tanhf(v0.y + g0.y + b.y);
                float t1x = tanhf(v1.x + g1.x + b.x), t1y = tanhf(v1.y + g1.y + b.y);
                float2 o0 = make_float2(fmaxf(z0.x * h0.x + (1.f - z0.x) * t0x, 0.f),
                                        fmaxf(z0.y * h0.y + (1.f - z0.y) * t0y, 0.f));
                float2 o1 = make_float2(fmaxf(z1.x * h1.x + (1.f - z1.x) * t1x, 0.f),
                                        fmaxf(z1.y * h1.y + (1.f - z1.y) * t1y, 0.f));
                *(float2*)(g_Hst + (size_t)r0 * 64 + colb) = o0;
                *(float2*)(g_Hst + (size_t)r1 * 64 + colb) = o1;
            } else if (EPI == 2) {
                float2 b = make_float2(a.bias[n0 + colb], a.bias[n0 + colb + 1]);
                float2 o0 = make_float2(fmaxf(v0.x + b.x, 0.f), fmaxf(v0.y + b.y, 0.f));
                float2 o1 = make_float2(fmaxf(v1.x + b.x, 0.f), fmaxf(v1.y + b.y, 0.f));
                *(float2*)(a.C + (size_t)r0 * a.ldc + n0 + colb) = o0;
                *(float2*)(a.C + (size_t)r1 * a.ldc + n0 + colb) = o1;
            } else {
                *(float2*)(a.C + (size_t)r0 * a.ldc + n0 + colb) = v0;
                *(float2*)(a.C + (size_t)r1 * a.ldc + n0 + colb) = v1;
            }
        }
    }
}

// ---------------- t = 0 special case (H0 = 0) ----------------
__global__ void k_step0(const float* __restrict__ G) {
    int i = blockIdx.x * 256 + threadIdx.x;
    int r = i >> 6, c = i & 63;
    float z = sigf(G[(size_t)r * 192 + c] + g_bc1[c]);
    float ht = tanhf(G[(size_t)r * 192 + 128 + c] + g_bc1[128 + c]);
    g_Hst[i] = fmaxf((1.f - z) * ht, 0.f);
}

// ---------------- final layer + softmax ----------------
__global__ void k_out(const float* __restrict__ A, const float* __restrict__ W3,
                      const float* __restrict__ b3, float* __restrict__ out) {
    int warp = threadIdx.x >> 5, lane = threadIdx.x & 31;
    int row = blockIdx.x * 8 + warp;
    float s0 = 0.f, s1 = 0.f;
    for (int k = lane; k < 320; k += 32) {
        float a = A[row * 320 + k];
        s0 += a * W3[k * 2];
        s1 += a * W3[k * 2 + 1];
    }
#pragma unroll
    for (int o = 16; o; o >>= 1) {
        s0 += __shfl_xor_sync(0xffffffffu, s0, o);
        s1 += __shfl_xor_sync(0xffffffffu, s1, o);
    }
    if (lane == 0) {
        float l0 = s0 + b3[0], l1 = s1 + b3[1];
        float m = fmaxf(l0, l1);
        float e0 = expf(l0 - m), e1 = expf(l1 - m);
        float inv = 1.f / (e0 + e1);
        out[row * 2] = e0 * inv;
        out[row * 2 + 1] = e1 * inv;
    }
}

// ---------------- launch ----------------
extern "C" void kernel_launch(void* const* d_in, const int* in_sizes, int n_in,
                              void* d_out, int out_size) {
    const float* x = (const float*)d_in[0];
    const int* ei = (const int*)d_in[1];
    const float* ew = (const float*)d_in[2];
    const float* Wxz = (const float*)d_in[3];  const float* bxz = (const float*)d_in[4];
    const float* Whz = (const float*)d_in[5];  const float* bhz = (const float*)d_in[6];
    const float* Wxr = (const float*)d_in[7];  const float* bxr = (const float*)d_in[8];
    const float* Whr = (const float*)d_in[9];  const float* bhr = (const float*)d_in[10];
    const float* Wxh = (const float*)d_in[11]; const float* bxh = (const float*)d_in[12];
    const float* Whh = (const float*)d_in[13]; const float* bhh = (const float*)d_in[14];
    const float* W1 = (const float*)d_in[15];  const float* b1 = (const float*)d_in[16];
    const float* W2 = (const float*)d_in[17];  const float* b2 = (const float*)d_in[18];
    const float* W3 = (const float*)d_in[19];  const float* b3 = (const float*)d_in[20];
    float* out = (float*)d_out;
    const int* src = ei;
    const int* dst = ei + NEDGE;

    float *pDeg, *pP1a, *pP2a, *pGxA, *pP3, *pP4, *pHR, *pH;
    float *pWBx, *pWBh, *pWB2, *pWB3, *pWB4, *pM1, *pM2;
    int* pFill;
    cudaGetSymbolAddress((void**)&pDeg, g_deg);
    cudaGetSymbolAddress((void**)&pFill, g_fill);
    cudaGetSymbolAddress((void**)&pP1a, g_P1a);
    cudaGetSymbolAddress((void**)&pP2a, g_P2a);
    cudaGetSymbolAddress((void**)&pGxA, g_GxA);
    cudaGetSymbolAddress((void**)&pP3, g_P3);
    cudaGetSymbolAddress((void**)&pP4, g_P4);
    cudaGetSymbolAddress((void**)&pHR, g_HR);
    cudaGetSymbolAddress((void**)&pH, g_Hst);
    cudaGetSymbolAddress((void**)&pWBx, g_WBx);
    cudaGetSymbolAddress((void**)&pWBh, g_WBh);
    cudaGetSymbolAddress((void**)&pWB2, g_WB2);
    cudaGetSymbolAddress((void**)&pWB3, g_WB3);
    cudaGetSymbolAddress((void**)&pWB4, g_WB4);
    cudaGetSymbolAddress((void**)&pM1, g_M1);
    cudaGetSymbolAddress((void**)&pM2, g_M2);

    const int SMB = (2 * AW + 2 * BW) * 4;  // 55296 bytes
    cudaFuncSetAttribute(k_mma<3, true>,  cudaFuncAttributeMaxDynamicSharedMemorySize, SMB);
    cudaFuncSetAttribute(k_mma<0, true>,  cudaFuncAttributeMaxDynamicSharedMemorySize, SMB);
    cudaFuncSetAttribute(k_mma<1, true>,  cudaFuncAttributeMaxDynamicSharedMemorySize, SMB);
    cudaFuncSetAttribute(k_mma<2, false>, cudaFuncAttributeMaxDynamicSharedMemorySize, SMB);

    // ---- preprocessing ----
    cudaMemsetAsync(pDeg, 0, BNN * sizeof(float));
    cudaMemsetAsync(pFill, 0, BNN * sizeof(int));
    k_degcnt<<<NEDGE / 256, 256>>>(src, dst, ew);
    k_dinv<<<BNN / 256, 256>>>();
    k_scanA<<<80, 1024>>>();
    k_scanB<<<1, 32>>>();
    k_scanC<<<80, 1024>>>();
    k_fillcsr<<<NEDGE / 256, 256>>>(src, dst, ew);
    k_packW<<<(1097920 + 255) / 256, 256>>>(Wxz, Wxr, Wxh, Whz, Whr, Whh,
                                            bxz, bxr, bxh, bhz, bhr, bhh, W1, W2);

    const dim3 pgAll(BNN * 16 / 128, NT);
    const dim3 pg1(BNN * 16 / 128, 1);

    // ---- X-side, hoisted out of the recurrence ----
    k_prop<<<pgAll, 128>>>((const float4*)x, (float4*)pP1a, 1.f, nullptr, 0.f);
    k_prop<<<pgAll, 128>>>((const float4*)pP1a, (float4*)pP2a, 2.f, (const float4*)x, -1.f);
    Args ax{};
    ax.a0 = x; ax.a1 = pP1a; ax.a2 = pP2a; ax.nk = 6; ax.ktot = 192;
    ax.B = pWBx; ax.C = pGxA; ax.ldc = 192;
    k_mma<3, true><<<dim3(3, MT / 128), 256, SMB>>>(ax);

    // ---- recurrence ----
    k_step0<<<BNN * 64 / 256, 256>>>(pGxA);

    Args ah{};
    ah.nk = 6; ah.ktot = 192; ah.B = pWBh;
    Args a2{};
    a2.nk = 6; a2.ktot = 192; a2.B = pWB2;

    for (int t = 1; t < NT; t++) {
        const float* Gt = pGxA + (size_t)t * BNN * 192;
        k_prop<<<pg1, 128>>>((const float4*)pH, (float4*)pP3, 1.f, nullptr, 0.f);
        k_prop<<<pg1, 128>>>((const float4*)pP3, (float4*)pP4, 2.f, (const float4*)pH, -1.f);
        ah.a0 = pH; ah.a1 = pP3; ah.a2 = pP4; ah.G = Gt;
        k_mma<0, true><<<dim3(2, 640), 256, SMB>>>(ah);
        k_prop<<<pg1, 128>>>((const float4*)pHR, (float4*)pP3, 1.f, nullptr, 0.f);
        k_prop<<<pg1, 128>>>((const float4*)pP3, (float4*)pP4, 2.f, (const float4*)pHR, -1.f);
        a2.a0 = pHR; a2.a1 = pP3; a2.a2 = pP4; a2.G = Gt;
        k_mma<1, true><<<dim3(1, 640), 256, SMB>>>(a2);
    }

    // ---- MLP head: H as [4096, 1280] ----
    Args m1{}; m1.a0 = pH; m1.astride = 1280; m1.nk = 40; m1.ktot = 1280;
    m1.B = pWB3; m1.bias = b1; m1.C = pM1; m1.ldc = 640;
    k_mma<2, false><<<dim3(10, 32), 256, SMB>>>(m1);
    Args m2{}; m2.a0 = pM1; m2.astride = 640; m2.nk = 20; m2.ktot = 640;
    m2.B = pWB4; m2.bias = b2; m2.C = pM2; m2.ldc = 320;
    k_mma<2, false><<<dim3(5, 32), 256, SMB>>>(m2);
    k_out<<<512, 256>>>(pM2, W3, b3, out);
}